// round 11
// baseline (speedup 1.0000x reference)
#include <cuda_runtime.h>
#include <cstdint>

#define B 8
#define L 512
#define H 20
#define D 1280
#define K 32

#define MV_BLOCKS   320                      // 16 warps * 320 = 5120 half-rows
#define TOPK_BASE   MV_BLOCKS                // 320
#define GATHER_BASE (MV_BLOCKS + 16)         // 336
#define REDUCE_BID  (MV_BLOCKS + 32)         // 352
#define NB          (REDUCE_BID + 1)         // 353 blocks, all resident in 1 wave

// Scratch (no allocations allowed in kernel_launch)
__device__ int   g_idx[2][B][K];            // top-K token indices per (rep, batch)
__device__ float g_up[2][4][D];             // j-half partials of u1,u2,v1,v2
__device__ float g_s[2][B][D];              // gather-SUM of selected rep rows
__device__ volatile int g_topk_flag[2][B];  // per-(rep,batch) "g_idx ready"
__device__ volatile int g_mv_done;          // matvec BLOCK completion counter
__device__ volatile int g_gather_done;      // gather BLOCK completion counter

// ---------------------------------------------------------------------------
// Warp-register bitonic sort, 32 u64 keys across lanes, DESCENDING.
// ---------------------------------------------------------------------------
__device__ __forceinline__ unsigned long long warp_sort_desc(
    unsigned long long key, int lane)
{
    unsigned long long v = ~key;
#pragma unroll
    for (int k = 2; k <= 32; k <<= 1) {
#pragma unroll
        for (int j = k >> 1; j > 0; j >>= 1) {
            unsigned long long other = __shfl_xor_sync(0xffffffffu, v, j);
            bool lower = (lane & j) == 0;
            bool up    = (lane & k) == 0;
            unsigned long long mn = (v < other) ? v : other;
            unsigned long long mx = (v < other) ? other : v;
            v = (lower == up) ? mn : mx;
        }
    }
    return ~v;
}

__device__ __forceinline__ float dot4(float4 a, float4 b) {
    return a.x * b.x + a.y * b.y + a.z * b.z + a.w * b.w;
}
__device__ __forceinline__ float4 add4(float4 a, float4 b) {
    return make_float4(a.x + b.x, a.y + b.y, a.z + b.z, a.w + b.w);
}

// ---------------------------------------------------------------------------
// ONE kernel. Block roles by blockIdx.x:
//   [0,320):   dual matvec half-rows -> g_up; ONE atomic per block
//   [320,336): top-K per (rep,batch) -> g_idx, per-(r,b) flag
//   [336,352): gather-sum (spins on OWN flag) -> g_s; ONE atomic per block
//   352:       prefetch inputs + bias dot, volatile-poll counters,
//              final reduce -> out, reset state
// ---------------------------------------------------------------------------
__global__ void __launch_bounds__(512) k_all(
    const float* __restrict__ rep1, const float* __restrict__ rep2,
    const float* __restrict__ attn1, const float* __restrict__ attn2,
    const int* __restrict__ pos,
    const float* __restrict__ cls_W, const float* __restrict__ env_W,
    const float* __restrict__ cls_b, const float* __restrict__ env_b,
    const float* __restrict__ clsclf_W, const float* __restrict__ envclf_W,
    const float* __restrict__ clsclf_b, const float* __restrict__ envclf_b,
    const float* __restrict__ cls_c1, const float* __restrict__ cls_c2,
    const float* __restrict__ env_c1, const float* __restrict__ env_c2,
    float* __restrict__ out)
{
    const int tid  = threadIdx.x;
    const int warp = tid >> 5;
    const int lane = tid & 31;

    if (blockIdx.x < MV_BLOCKS) {
        // ---- dual matvec: one warp per HALF row (640 floats) --------------
        const int gw   = blockIdx.x * 16 + warp;   // 0..5119
        const int half = gw & 1;
        const int grow = gw >> 1;                  // 0..2559
        const int mat  = grow >= D;
        const int row  = grow - mat * D;
        const float* W  = mat ? env_W    : cls_W;
        const float* wc = mat ? envclf_W : clsclf_W;
        const float* c1 = mat ? env_c1   : cls_c1;
        const float* c2 = mat ? env_c2   : cls_c2;
        const float* Wr = W + (size_t)row * D;
        const int j0 = half * (D / 2) + lane * 4;

        float4 wv[5];
#pragma unroll
        for (int it = 0; it < 5; ++it)
            wv[it] = *(const float4*)(Wr + j0 + it * 128);

        float a1 = 0.f, a2 = 0.f;
#pragma unroll
        for (int it = 0; it < 5; ++it) {
            const int j = j0 + it * 128;
            float4 wcv = *(const float4*)(wc + j);
            float4 c1v = *(const float4*)(c1 + j);
            float4 c2v = *(const float4*)(c2 + j);
            float sx = wv[it].x * wcv.x, sy = wv[it].y * wcv.y,
                  sz = wv[it].z * wcv.z, sw = wv[it].w * wcv.w;
            a1 += sx * c1v.x + sy * c1v.y + sz * c1v.z + sw * c1v.w;
            a2 += sx * c2v.x + sy * c2v.y + sz * c2v.z + sw * c2v.w;
        }
#pragma unroll
        for (int o = 16; o; o >>= 1) {
            a1 += __shfl_xor_sync(0xffffffffu, a1, o);
            a2 += __shfl_xor_sync(0xffffffffu, a2, o);
        }
        if (lane == 0) {
            g_up[half][mat * 2 + 0][row] = a1;
            g_up[half][mat * 2 + 1][row] = a2;
        }
        // one completion signal per BLOCK (not per warp)
        __syncthreads();
        if (tid == 0) {
            __threadfence();
            atomicAdd((int*)&g_mv_done, 1);
        }
    }
    else if (blockIdx.x < GATHER_BASE) {
        // ---- top-K for one (rep, batch) ------------------------------------
        const int tb = blockIdx.x - TOPK_BASE;   // 0..15
        const int b  = tb & 7;
        const int r  = tb >> 3;
        const float* attn = r ? attn2 : attn1;
        const int l = tid;                       // token 0..511
        const int p = pos[b];

        const float* base = attn + ((size_t)b * H) * (size_t)(L * L)
                                 + (size_t)p * L + l;
        float s = 0.f;
#pragma unroll
        for (int h = 0; h < H; ++h)
            s += base[(size_t)h * (L * L)];

        unsigned fb = __float_as_uint(s * (1.0f / H));
        fb = (fb & 0x80000000u) ? ~fb : (fb | 0x80000000u);
        unsigned long long key =
            ((unsigned long long)fb << 32) | (unsigned)(L - 1 - l);

        key = warp_sort_desc(key, lane);

        __shared__ unsigned long long sorted[16][32];
        sorted[warp][lane] = key;
        __syncthreads();

        if (warp == 0) {
            unsigned long long h = (lane < 16) ? sorted[lane][0] : 0ull;
            int ptr = 0;
#pragma unroll
            for (int i = 0; i < K; ++i) {
                unsigned long long m = h;
#pragma unroll
                for (int o = 8; o; o >>= 1) {
                    unsigned long long other = __shfl_xor_sync(0xffffffffu, m, o);
                    if (other > m) m = other;
                }
                m = __shfl_sync(0xffffffffu, m, 0);
                if (h == m) {
                    g_idx[r][b][i] = L - 1 - (int)(m & 0xffffffffu);
                    ++ptr;
                    h = (ptr < 32) ? sorted[lane][ptr] : 0ull;
                }
            }
            __syncwarp();
            if (lane == 0) {
                __threadfence();
                g_topk_flag[r][b] = 1;
            }
        }
    }
    else if (blockIdx.x < REDUCE_BID) {
        // ---- gather-sum for one (rep, batch): waits only on its own flag --
        const int tb = blockIdx.x - GATHER_BASE;   // 0..15
        const int b  = tb & 7;
        const int r  = tb >> 3;
        const float* rep  = r ? rep2 : rep1;
        const float* repb = rep + (size_t)b * L * D;

        if (tid == 0) {
            while (g_topk_flag[r][b] == 0)
                __nanosleep(32);
            __threadfence();                   // acquire g_idx
        }
        __syncthreads();

        const int myrow = g_idx[r][b][lane];
        float a0 = 0.f, a1 = 0.f, a2 = 0.f;
#pragma unroll
        for (int t = 0; t < K; ++t) {
            const int row = __shfl_sync(0xffffffffu, myrow, t);
            const float* rp = repb + (size_t)row * D;
            a0 += rp[tid];
            a1 += rp[tid + 512];
            if (tid < 256) a2 += rp[tid + 1024];
        }
        g_s[r][b][tid]       = a0;
        g_s[r][b][tid + 512] = a1;
        if (tid < 256) g_s[r][b][tid + 1024] = a2;

        __syncthreads();
        if (tid == 0) {
            __threadfence();                   // release g_s
            atomicAdd((int*)&g_gather_done, 1);
        }
    }
    else {
        // ---- dedicated reduce block ----------------------------------------
        __shared__ float sA[8], sB[8], sW[16];
        const int g = warp >> 3;          // 0 = cls pair, 1 = env pair
        const int b = warp & 7;

        // (a) prefetch input-only data while producers run:
        //     cls warps preload token-0 rows; all threads do the bias dot.
        float4 rv1[10], rv2[10];
        if (g == 0) {
            const float* r1 = rep1 + (size_t)b * L * D;
            const float* r2 = rep2 + (size_t)b * L * D;
#pragma unroll
            for (int it = 0; it < 10; ++it) {
                rv1[it] = *(const float4*)(r1 + lane * 4 + it * 128);
                rv2[it] = *(const float4*)(r2 + lane * 4 + it * 128);
            }
        }
        float bias_acc = 0.f;
        for (int d = tid; d < D; d += 512)
            bias_acc += cls_b[d] * (cls_c1[d] + cls_c2[d]) * clsclf_W[d]
                      + env_b[d] * (env_c1[d] + env_c2[d]) * envclf_W[d];
#pragma unroll
        for (int o = 16; o; o >>= 1)
            bias_acc += __shfl_xor_sync(0xffffffffu, bias_acc, o);
        if (lane == 0) sW[warp] = bias_acc;

        // (b) wait: plain volatile polls (no atomic RMW contention).
        if (tid == 0) {
            while (g_mv_done < MV_BLOCKS || g_gather_done < 16)
                __nanosleep(128);
            __threadfence();                   // acquire g_up / g_s
        }
        __syncthreads();

        // (c) final dots (u/v and g_s are L2-hot now).
        float acc = 0.f;
        if (g == 0) {
#pragma unroll
            for (int it = 0; it < 10; ++it) {
                const int i = lane * 4 + it * 128;
                float4 u1 = add4(*(const float4*)(g_up[0][0] + i),
                                 *(const float4*)(g_up[1][0] + i));
                float4 u2 = add4(*(const float4*)(g_up[0][1] + i),
                                 *(const float4*)(g_up[1][1] + i));
                acc += dot4(rv1[it], u1) + dot4(rv2[it], u2);
            }
        } else {
#pragma unroll
            for (int it = 0; it < 10; ++it) {
                const int i = lane * 4 + it * 128;
                float4 v1 = add4(*(const float4*)(g_up[0][2] + i),
                                 *(const float4*)(g_up[1][2] + i));
                float4 v2 = add4(*(const float4*)(g_up[0][3] + i),
                                 *(const float4*)(g_up[1][3] + i));
                acc += dot4(*(const float4*)(g_s[0][b] + i), v1)
                     + dot4(*(const float4*)(g_s[1][b] + i), v2);
            }
        }
#pragma unroll
        for (int o = 16; o; o >>= 1)
            acc += __shfl_xor_sync(0xffffffffu, acc, o);
        if (lane == 0) {
            if (g == 0) sA[b] = acc; else sB[b] = acc;
        }
        __syncthreads();

        if (tid < 8) {
            float bias = 0.f;
#pragma unroll
            for (int w = 0; w < 16; ++w) bias += sW[w];
            out[tid] = (sA[tid] + sB[tid] * (1.0f / K)
                        + bias + clsclf_b[0] + envclf_b[0]) * 0.5f;
        }
        if (tid == 0) {
            // reset protocol state for the next graph replay
            g_mv_done = 0;
            g_gather_done = 0;
            for (int i = 0; i < 2 * B; ++i)
                ((volatile int*)&g_topk_flag[0][0])[i] = 0;
            __threadfence();
        }
    }
}

// ---------------------------------------------------------------------------
extern "C" void kernel_launch(void* const* d_in, const int* in_sizes, int n_in,
                              void* d_out, int out_size)
{
    const float* rep1     = (const float*)d_in[0];
    const float* rep2     = (const float*)d_in[1];
    const float* attn1    = (const float*)d_in[2];
    const float* attn2    = (const float*)d_in[3];
    const int*   pos      = (const int*)  d_in[4];
    const float* cls_W    = (const float*)d_in[5];
    const float* cls_b    = (const float*)d_in[6];
    const float* env_W    = (const float*)d_in[7];
    const float* env_b    = (const float*)d_in[8];
    const float* clsclf_W = (const float*)d_in[9];
    const float* clsclf_b = (const float*)d_in[10];
    const float* envclf_W = (const float*)d_in[11];
    const float* envclf_b = (const float*)d_in[12];
    const float* cls_c1   = (const float*)d_in[13];
    const float* cls_c2   = (const float*)d_in[14];
    const float* env_c1   = (const float*)d_in[15];
    const float* env_c2   = (const float*)d_in[16];
    float* out = (float*)d_out;

    k_all<<<NB, 512>>>(rep1, rep2, attn1, attn2, pos,
                       cls_W, env_W, cls_b, env_b,
                       clsclf_W, envclf_W, clsclf_b, envclf_b,
                       cls_c1, cls_c2, env_c1, env_c2, out);
}

// round 12
// speedup vs baseline: 1.4138x; 1.4138x over previous
#include <cuda_runtime.h>
#include <cstdint>

#define B 8
#define L 512
#define H 20
#define D 1280
#define K 32

#define MATVEC_BLOCKS 320   // 16 warps * 320 = 5120 half-rows = 2*2560 rows
#define TOPK_BLOCKS   16    // 2 reps * 8 batches
#define BIAS_BLOCKS   1
#define FUSED_BLOCKS  (MATVEC_BLOCKS + TOPK_BLOCKS + BIAS_BLOCKS)

#define GD_BLOCKS     64    // gather-dot: 2 reps * 8 batches * 4 row-quarters
#define CLS_BLOCKS    8     // one per batch
#define DOT_BLOCKS    (GD_BLOCKS + CLS_BLOCKS)   // 72

// Scratch (no allocations allowed in kernel_launch)
__device__ int   g_idx[2][B][K];    // top-K token indices per (rep, batch)
__device__ float g_up[2][4][D];     // j-half partials of u1,u2,v1,v2
__device__ float g_part[GD_BLOCKS]; // per (r,b,q) partial env dots
__device__ float g_cls[B];          // per-batch cls dots
__device__ float g_bias;            // batch-independent bias dot
__device__ int   g_ctr;             // completion counter (self-resetting)

// ---------------------------------------------------------------------------
// Warp-register bitonic sort, 32 u64 keys across lanes, DESCENDING.
// ---------------------------------------------------------------------------
__device__ __forceinline__ unsigned long long warp_sort_desc(
    unsigned long long key, int lane)
{
    unsigned long long v = ~key;
#pragma unroll
    for (int k = 2; k <= 32; k <<= 1) {
#pragma unroll
        for (int j = k >> 1; j > 0; j >>= 1) {
            unsigned long long other = __shfl_xor_sync(0xffffffffu, v, j);
            bool lower = (lane & j) == 0;
            bool up    = (lane & k) == 0;
            unsigned long long mn = (v < other) ? v : other;
            unsigned long long mx = (v < other) ? other : v;
            v = (lower == up) ? mn : mx;
        }
    }
    return ~v;   // lane i holds i-th LARGEST original key
}

// ---------------------------------------------------------------------------
// Kernel 1 (fused): [0,320) dual matvec half-rows; [320,336) top-K; 336 bias.
// (Identical to the 17.2us R5 version.)
// ---------------------------------------------------------------------------
__global__ void __launch_bounds__(512) k_fused(
    const float* __restrict__ attn1, const float* __restrict__ attn2,
    const int* __restrict__ pos,
    const float* __restrict__ cls_W, const float* __restrict__ env_W,
    const float* __restrict__ cls_b, const float* __restrict__ env_b,
    const float* __restrict__ clsclf_W, const float* __restrict__ envclf_W,
    const float* __restrict__ cls_c1, const float* __restrict__ cls_c2,
    const float* __restrict__ env_c1, const float* __restrict__ env_c2)
{
    const int warp = threadIdx.x >> 5;
    const int lane = threadIdx.x & 31;

    if (blockIdx.x < MATVEC_BLOCKS) {
        const int gw   = blockIdx.x * 16 + warp;   // 0..5119
        const int half = gw & 1;
        const int grow = gw >> 1;                  // 0..2559
        const int mat  = grow >= D;
        const int row  = grow - mat * D;
        const float* W  = mat ? env_W    : cls_W;
        const float* wc = mat ? envclf_W : clsclf_W;
        const float* c1 = mat ? env_c1   : cls_c1;
        const float* c2 = mat ? env_c2   : cls_c2;
        const float* Wr = W + (size_t)row * D;
        const int j0 = half * (D / 2) + lane * 4;

        float4 wv[5];
#pragma unroll
        for (int it = 0; it < 5; ++it)
            wv[it] = *(const float4*)(Wr + j0 + it * 128);

        float a1 = 0.f, a2 = 0.f;
#pragma unroll
        for (int it = 0; it < 5; ++it) {
            const int j = j0 + it * 128;
            float4 wcv = *(const float4*)(wc + j);
            float4 c1v = *(const float4*)(c1 + j);
            float4 c2v = *(const float4*)(c2 + j);
            float sx = wv[it].x * wcv.x, sy = wv[it].y * wcv.y,
                  sz = wv[it].z * wcv.z, sw = wv[it].w * wcv.w;
            a1 += sx * c1v.x + sy * c1v.y + sz * c1v.z + sw * c1v.w;
            a2 += sx * c2v.x + sy * c2v.y + sz * c2v.z + sw * c2v.w;
        }
#pragma unroll
        for (int o = 16; o; o >>= 1) {
            a1 += __shfl_xor_sync(0xffffffffu, a1, o);
            a2 += __shfl_xor_sync(0xffffffffu, a2, o);
        }
        if (lane == 0) {
            g_up[half][mat * 2 + 0][row] = a1;
            g_up[half][mat * 2 + 1][row] = a2;
        }
        return;
    }

    if (blockIdx.x == MATVEC_BLOCKS + TOPK_BLOCKS) {
        if (warp != 0) return;
        float a = 0.f;
        for (int d = lane; d < D; d += 32)
            a += cls_b[d] * (cls_c1[d] + cls_c2[d]) * clsclf_W[d]
               + env_b[d] * (env_c1[d] + env_c2[d]) * envclf_W[d];
#pragma unroll
        for (int o = 16; o; o >>= 1)
            a += __shfl_xor_sync(0xffffffffu, a, o);
        if (lane == 0) g_bias = a;
        return;
    }

    // --- top-K for one (rep, batch) ---
    const int tb = blockIdx.x - MATVEC_BLOCKS;   // 0..15
    const int b  = tb & 7;
    const int r  = tb >> 3;
    const float* attn = r ? attn2 : attn1;
    const int l = threadIdx.x;                   // token 0..511
    const int p = pos[b];

    const float* base = attn + ((size_t)b * H) * (size_t)(L * L)
                             + (size_t)p * L + l;
    float s = 0.f;
#pragma unroll
    for (int h = 0; h < H; ++h)
        s += base[(size_t)h * (L * L)];

    unsigned fb = __float_as_uint(s * (1.0f / H));
    fb = (fb & 0x80000000u) ? ~fb : (fb | 0x80000000u);
    unsigned long long key =
        ((unsigned long long)fb << 32) | (unsigned)(L - 1 - l);

    key = warp_sort_desc(key, lane);

    __shared__ unsigned long long sorted[16][32];
    sorted[warp][lane] = key;
    __syncthreads();

    if (warp == 0) {
        unsigned long long h = (lane < 16) ? sorted[lane][0] : 0ull;
        int ptr = 0;
#pragma unroll
        for (int i = 0; i < K; ++i) {
            unsigned long long m = h;
#pragma unroll
            for (int o = 8; o; o >>= 1) {
                unsigned long long other = __shfl_xor_sync(0xffffffffu, m, o);
                if (other > m) m = other;
            }
            m = __shfl_sync(0xffffffffu, m, 0);
            if (h == m) {
                g_idx[r][b][i] = L - 1 - (int)(m & 0xffffffffu);
                ++ptr;
                h = (ptr < 32) ? sorted[lane][ptr] : 0ull;
            }
        }
    }
}

// ---------------------------------------------------------------------------
// block-reduce a scalar over 512 threads (16 warps) -> thread 0
// ---------------------------------------------------------------------------
__device__ __forceinline__ float block_reduce_512(float v, float* red,
                                                  int warp, int lane)
{
#pragma unroll
    for (int o = 16; o; o >>= 1)
        v += __shfl_xor_sync(0xffffffffu, v, o);
    if (lane == 0) red[warp] = v;
    __syncthreads();
    float t = 0.f;
    if (warp == 0) {
        t = (lane < 16) ? red[lane] : 0.f;
#pragma unroll
        for (int o = 8; o; o >>= 1)
            t += __shfl_xor_sync(0xffffffffu, t, o);
    }
    return t;   // valid in warp 0
}

// ---------------------------------------------------------------------------
// Kernel 2: 72 blocks, 512 threads.
//   [0,64):  gather-dot. bid -> r=bid>>5, b=(bid>>2)&7, q=bid&3.
//            Sum rows g_idx[r][b][8q..8q+7] column-wise (24 independent
//            coalesced loads/thread), dot against v_r, block-reduce.
//   [64,72): cls dot for batch b: rep1[b,0].u1 + rep2[b,0].u2.
//   Last finished block combines everything -> out[].
// ---------------------------------------------------------------------------
__global__ void __launch_bounds__(512) k_dots(
    const float* __restrict__ rep1, const float* __restrict__ rep2,
    const float* __restrict__ clsclf_b, const float* __restrict__ envclf_b,
    float* __restrict__ out)
{
    const int tid  = threadIdx.x;
    const int warp = tid >> 5;
    const int lane = tid & 31;

    __shared__ float red[16];

    if (blockIdx.x < GD_BLOCKS) {
        const int r = blockIdx.x >> 5;
        const int b = (blockIdx.x >> 2) & 7;
        const int q = blockIdx.x & 3;
        const float* rep  = r ? rep2 : rep1;
        const float* repb = rep + (size_t)b * L * D;
        const int vi = 2 + r;

        // 8 row indices (L2 broadcast load)
        int rows[8];
#pragma unroll
        for (int j = 0; j < 8; ++j)
            rows[j] = g_idx[r][b][q * 8 + j];

        // column-wise sum of 8 rows; 24 independent coalesced loads/thread
        float a0 = 0.f, a1 = 0.f, a2 = 0.f;
#pragma unroll
        for (int j = 0; j < 8; ++j) {
            const float* rp = repb + (size_t)rows[j] * D;
            a0 += rp[tid];
            a1 += rp[tid + 512];
            if (tid < 256) a2 += rp[tid + 1024];
        }

        // dot partial column-sums against v (L2-hot)
        float p = a0 * (g_up[0][vi][tid]        + g_up[1][vi][tid])
                + a1 * (g_up[0][vi][tid + 512]  + g_up[1][vi][tid + 512]);
        if (tid < 256)
            p += a2 * (g_up[0][vi][tid + 1024] + g_up[1][vi][tid + 1024]);

        float t = block_reduce_512(p, red, warp, lane);
        if (tid == 0) g_part[blockIdx.x] = t;
    }
    else {
        // ---- cls dot for batch b ----
        const int b = blockIdx.x - GD_BLOCKS;
        const float* r1 = rep1 + (size_t)b * L * D;   // token-0 rows
        const float* r2 = rep2 + (size_t)b * L * D;

        float p = r1[tid]       * (g_up[0][0][tid]       + g_up[1][0][tid])
                + r2[tid]       * (g_up[0][1][tid]       + g_up[1][1][tid])
                + r1[tid + 512] * (g_up[0][0][tid + 512] + g_up[1][0][tid + 512])
                + r2[tid + 512] * (g_up[0][1][tid + 512] + g_up[1][1][tid + 512]);
        if (tid < 256)
            p += r1[tid + 1024] * (g_up[0][0][tid + 1024] + g_up[1][0][tid + 1024])
               + r2[tid + 1024] * (g_up[0][1][tid + 1024] + g_up[1][1][tid + 1024]);

        float t = block_reduce_512(p, red, warp, lane);
        if (tid == 0) g_cls[b] = t;
    }

    // ---- last-block-done final combine ----
    __syncthreads();
    __shared__ int is_last;
    if (tid == 0) {
        __threadfence();
        is_last = (atomicAdd(&g_ctr, 1) == DOT_BLOCKS - 1);
    }
    __syncthreads();
    if (!is_last) return;

    __threadfence();   // acquire all partials
    if (tid < B) {
        const int b = tid;
        float env = 0.f;
#pragma unroll
        for (int r = 0; r < 2; ++r)
#pragma unroll
            for (int q = 0; q < 4; ++q)
                env += g_part[r * 32 + b * 4 + q];
        out[b] = (g_cls[b] + env * (1.0f / K)
                  + g_bias + clsclf_b[0] + envclf_b[0]) * 0.5f;
    }
    if (tid == 0) g_ctr = 0;   // reset for next graph replay
}

// ---------------------------------------------------------------------------
extern "C" void kernel_launch(void* const* d_in, const int* in_sizes, int n_in,
                              void* d_out, int out_size)
{
    const float* rep1     = (const float*)d_in[0];
    const float* rep2     = (const float*)d_in[1];
    const float* attn1    = (const float*)d_in[2];
    const float* attn2    = (const float*)d_in[3];
    const int*   pos      = (const int*)  d_in[4];
    const float* cls_W    = (const float*)d_in[5];
    const float* cls_b    = (const float*)d_in[6];
    const float* env_W    = (const float*)d_in[7];
    const float* env_b    = (const float*)d_in[8];
    const float* clsclf_W = (const float*)d_in[9];
    const float* clsclf_b = (const float*)d_in[10];
    const float* envclf_W = (const float*)d_in[11];
    const float* envclf_b = (const float*)d_in[12];
    const float* cls_c1   = (const float*)d_in[13];
    const float* cls_c2   = (const float*)d_in[14];
    const float* env_c1   = (const float*)d_in[15];
    const float* env_c2   = (const float*)d_in[16];
    float* out = (float*)d_out;

    k_fused<<<FUSED_BLOCKS, 512>>>(
        attn1, attn2, pos, cls_W, env_W, cls_b, env_b,
        clsclf_W, envclf_W, cls_c1, cls_c2, env_c1, env_c2);

    k_dots<<<DOT_BLOCKS, 512>>>(rep1, rep2, clsclf_b, envclf_b, out);
}